// round 16
// baseline (speedup 1.0000x reference)
#include <cuda_runtime.h>
#include <cstdint>

// Problem constants
#define NV   128
#define NN   512
#define LL   4096
#define GG   32      // CTAs (persistent, co-resident)
#define JC   16      // columns per CTA
#define TPB  256

// Tagged vector buffers: high 32 bits = step tag, low 32 = float bits.
__device__ unsigned long long g_u[2][NN];
__device__ float  g_pdot[LL * GG];       // per-step, per-CTA emission partials
__device__ double g_factor[LL];          // per-step emission dot (double)
// Repacked transfer: slice (v,g) is column-major [16 cols][512 rows], contiguous 32KB.
__device__ float g_tx[(size_t)NV * GG * NN * JC];

__device__ __forceinline__ unsigned long long ld_poll(const unsigned long long* p) {
    unsigned long long v;
    asm volatile("ld.relaxed.gpu.global.b64 %0, [%1];" : "=l"(v) : "l"(p));
    return v;
}
__device__ __forceinline__ void st_pub(unsigned long long* p, unsigned long long v) {
    asm volatile("st.relaxed.gpu.global.b64 [%0], %1;" :: "l"(p), "l"(v));
}

// Reset tags + seed u_0 = start. Runs each launch (graph replay safe).
__global__ void init_kernel(const float* __restrict__ start) {
    int j = threadIdx.x;
    if (j < NN) {
        st_pub(&g_u[1][j], 0xFFFFFFFF00000000ull);
        unsigned long long v = (unsigned long long)__float_as_uint(start[j]); // tag 0
        st_pub(&g_u[0][j], v);
    }
}

// Repack transfer -> g_tx, column-major per slice, via smem-tiled transpose.
__global__ void transform_kernel(const float* __restrict__ transfer) {
    __shared__ float tile[64 * 17];                 // 64 rows x 16 cols, padded
    const int v  = blockIdx.x >> 5;
    const int g  = blockIdx.x & 31;
    const int tid = threadIdx.x;
    const float* src = transfer + (size_t)v * (NN * NN) + g * JC;
    float* dst = g_tx + (size_t)blockIdx.x * (NN * JC);

    for (int rt = 0; rt < NN; rt += 64) {
        __syncthreads();
        #pragma unroll
        for (int it = 0; it < 4; ++it) {            // 1024 elems / 256 threads
            int idx = tid + it * TPB;
            int r = idx >> 4, c = idx & 15;
            tile[r * 17 + c] = src[(size_t)(rt + r) * NN + c];
        }
        __syncthreads();
        #pragma unroll
        for (int it = 0; it < 4; ++it) {
            int idx = tid + it * TPB;
            int c = idx >> 6, rr = idx & 63;        // coalesced write over rr
            dst[c * NN + rt + rr] = tile[rr * 17 + c];
        }
    }
}

__global__ void __launch_bounds__(TPB, 1)
walk_kernel(const int* __restrict__ tokens,
            const float* __restrict__ probs) {
    __shared__ __align__(16) float uvec[NN];
    __shared__ int stok[LL];

    const int tid  = threadIdx.x;
    const int g    = blockIdx.x;
    const int j0   = g * JC;
    const int lane = tid & 31, wid = tid >> 5;
    const int l15  = lane & 15;
    const int ch   = lane >> 4;                     // column-half: 0 or 1
    const int mycol = 2 * wid + ch;                 // local col 0..15
    const bool isPub = (l15 == 0);                  // lanes 0 and 16 publish
    const bool isEmi = (wid == 1 && lane < JC);     // emission crew

    for (int i = tid; i < LL; i += TPB) stok[i] = tokens[i];
    __syncthreads();

    // Matrix register double-buffer: 8 float4 per thread.
    float4 A[8], B[8];
    {
        const float* b = g_tx + (size_t)(stok[0] * GG + g) * (NN * JC)
                       + (size_t)mycol * NN + l15 * 4;
        #pragma unroll
        for (int k = 0; k < 8; ++k)
            A[k] = *reinterpret_cast<const float4*>(b + 64 * k);
    }
    // Emission probs pipeline register: at body(t) holds probs[stok[t-1]][j0+lane].
    float pvE = 0.f;
    if (isEmi) pvE = __ldg(&probs[(size_t)stok[0] * NN + j0 + lane]);

    auto body = [&](int t, float4* cur, float4* nxt) {
        // ---- poll u_{t-1} first (clean L1tex queue), 3-deep pipelined
        {
            const unsigned wantTag = (unsigned)(t - 1);
            const int par = (t - 1) & 1;
            const unsigned long long* p0 = &g_u[par][tid];
            const unsigned long long* p1 = &g_u[par][tid + TPB];
            unsigned long long a0 = ld_poll(p0), a1 = ld_poll(p1);
            unsigned long long b0 = ld_poll(p0), b1 = ld_poll(p1);
            unsigned long long c0 = ld_poll(p0), c1 = ld_poll(p1);
            unsigned long long v0, v1;
            for (;;) {
                if ((unsigned)(a0 >> 32) == wantTag && (unsigned)(a1 >> 32) == wantTag) {
                    v0 = a0; v1 = a1; break;
                }
                a0 = ld_poll(p0); a1 = ld_poll(p1);
                if ((unsigned)(b0 >> 32) == wantTag && (unsigned)(b1 >> 32) == wantTag) {
                    v0 = b0; v1 = b1; break;
                }
                b0 = ld_poll(p0); b1 = ld_poll(p1);
                if ((unsigned)(c0 >> 32) == wantTag && (unsigned)(c1 >> 32) == wantTag) {
                    v0 = c0; v1 = c1; break;
                }
                c0 = ld_poll(p0); c1 = ld_poll(p1);
            }
            uvec[tid]       = __uint_as_float((unsigned)v0);
            uvec[tid + TPB] = __uint_as_float((unsigned)v1);
        }

        // ---- prefetch step t+1 matrix (drains during GEMV)
        if (t < LL) {
            const int tok2 = stok[t];
            const float* b = g_tx + (size_t)(tok2 * GG + g) * (NN * JC)
                           + (size_t)mycol * NN + l15 * 4;
            #pragma unroll
            for (int k = 0; k < 8; ++k)
                nxt[k] = *reinterpret_cast<const float4*>(b + 64 * k);
        }
        __syncthreads();   // uvec = u_{t-1}, complete and visible

        // ---- emission factor t-1 = uvec . probs[stok[t-1]] (warp 1 crew).
        //      Reads the SAME barrier-ordered uvec the GEMV consumes.
        if (isEmi) {
            float e = uvec[j0 + lane] * pvE;
            #pragma unroll
            for (int d = 1; d < JC; d <<= 1)
                e += __shfl_xor_sync(0x0000FFFFu, e, d);
            if (lane == 0) g_pdot[(t - 1) * GG + g] = e;
            if (t < LL)    // reload pipeline register for next body
                pvE = __ldg(&probs[(size_t)stok[t] * NN + j0 + lane]);
        }

        // ---- per-lane partial of column mycol (4 independent FMA chains)
        float4 acc = make_float4(0.f, 0.f, 0.f, 0.f);
        #pragma unroll
        for (int k = 0; k < 8; ++k) {
            float4 uu = *reinterpret_cast<const float4*>(&uvec[l15 * 4 + 64 * k]);
            float4 m  = cur[k];
            acc.x = fmaf(uu.x, m.x, acc.x);
            acc.y = fmaf(uu.y, m.y, acc.y);
            acc.z = fmaf(uu.z, m.z, acc.z);
            acc.w = fmaf(uu.w, m.w, acc.w);
        }
        float a = (acc.x + acc.y) + (acc.z + acc.w);
        // half-warp reduce (16 lanes) -> every lane holds its column sum
        #pragma unroll
        for (int d = 1; d < 16; d <<= 1)
            a += __shfl_xor_sync(0xffffffffu, a, d);

        // ---- publish directly from lanes 0/16 (fused tag+data)
        if (isPub) {
            unsigned long long pvw =
                ((unsigned long long)(unsigned)t << 32) |
                (unsigned long long)__float_as_uint(a);
            st_pub(&g_u[t & 1][j0 + mycol], pvw);
        }

        // ---- RACE FENCE: no thread may re-enter the poll (and overwrite
        //      uvec) until every warp has finished its uvec reads for step t.
        //      Removing this barrier was the R11-R15 output1 corruption:
        //      a fast warp's poll at t+1 depends only on REMOTE publishes,
        //      so without the barrier it clobbers uvec under slow siblings.
        __syncthreads();
    };

    #pragma unroll 1
    for (int t = 1; t <= LL; t += 2) {   // LL even
        body(t,     A, B);
        body(t + 1, B, A);
    }
}

// One warp per step t=0..LL-1: sum 32 per-CTA partials in double.
__global__ void factor_kernel() {
    const int wid = threadIdx.x >> 5, lane = threadIdx.x & 31;
    const int t = blockIdx.x * 8 + wid;          // grid 512 x 256 -> t in [0,4096)
    if (t >= LL) return;
    double e = (double)g_pdot[t * GG + lane];
    #pragma unroll
    for (int d = 16; d > 0; d >>= 1)
        e += __shfl_xor_sync(0xffffffffu, e, d);
    if (lane == 0) g_factor[t] = e;
}

__global__ void finalize_kernel(const float* __restrict__ finals,
                                float* __restrict__ out, int out_size) {
    __shared__ double sd[TPB];
    const int tid = threadIdx.x;

    // product of per-step factors, t=0..LL-1
    double lp = 1.0;
    for (int t = tid; t < LL; t += TPB)
        lp *= g_factor[t];
    sd[tid] = lp; __syncthreads();
    for (int d = TPB / 2; d > 0; d >>= 1) {
        if (tid < d) sd[tid] *= sd[tid + d];
        __syncthreads();
    }
    double totprod = sd[0];
    __syncthreads();

    // final u (LL even -> parity 0), finals dot, outputs
    double fp = 0.0;
    for (int j = tid; j < NN; j += TPB) {
        unsigned long long v = g_u[0][j];
        float uv = __uint_as_float((unsigned)v);
        if (j < out_size) out[j] = uv;
        fp += (double)uv * (double)finals[j];
    }
    sd[tid] = fp; __syncthreads();
    for (int d = TPB / 2; d > 0; d >>= 1) {
        if (tid < d) sd[tid] += sd[tid + d];
        __syncthreads();
    }
    if (tid == 0 && out_size > NN) out[NN] = (float)(totprod * sd[0]);
}

extern "C" void kernel_launch(void* const* d_in, const int* in_sizes, int n_in,
                              void* d_out, int out_size) {
    const int*   tokens   = (const int*)d_in[0];
    const float* start    = (const float*)d_in[1];
    const float* transfer = (const float*)d_in[2];
    const float* probs    = (const float*)d_in[3];
    const float* finals   = (const float*)d_in[4];
    float* out = (float*)d_out;

    init_kernel<<<1, 512>>>(start);
    transform_kernel<<<NV * GG, TPB>>>(transfer);
    walk_kernel<<<GG, TPB>>>(tokens, probs);
    factor_kernel<<<512, 256>>>();
    finalize_kernel<<<1, TPB>>>(finals, out, out_size);
}